// round 10
// baseline (speedup 1.0000x reference)
#include <cuda_runtime.h>
#include <math.h>

// Problem constants
#define PN   4096
#define TT   128
#define AA   32
#define KEL  409          // int(4096 * 0.1)
#define KPAD 416          // 32 * 13, zero-weight padded
#define INFF 1e30f

// ---------------- scratch (no allocations allowed) ----------------
__device__ float g_dists[PN];
__device__ int   g_eidx[KPAD];
__device__ float g_edist[KEL];
__device__ float g_w[KPAD];
__device__ float g_scalars[2];   // [0] = ssum, [1] = 1/(ssum+1e-9)

// =====================================================================
// Kernel A: DTW min-plus DP. Two problems per warp via 16-lane SEGMENTS
// (lanes 0-15 = problem A, lanes 16-31 = problem B); each lane owns 8
// consecutive columns. Row recurrence
//   new[j] = min(min(prev[j+1],prev[j]), new[j-1]) + c[j]
// solved per row as: s = prefix_sum(c); new[j] = s[j] + prefmin(m-s_ex).
// Segmented 16-wide scans take 4 shuffle steps, and each shuffle serves
// both problems: 5 SHFL per problem-row (vs 12 before). Row i+1's +scan
// is computed during row i's min-scan; loads prefetched 2 rows ahead.
// =====================================================================
__global__ void __launch_bounds__(256) dtw_kernel(const float* __restrict__ obs) {
    const unsigned FULL = 0xffffffffu;
    int warpId = (blockIdx.x * blockDim.x + threadIdx.x) >> 5;
    int lane   = threadIdx.x & 31;
    if (warpId >= PN / 2) return;

    int seg = lane >> 4;       // 0 = problem A, 1 = problem B
    int sl  = lane & 15;       // lane within segment

    const float4* cb = (const float4*)(obs + (size_t)(2 * warpId + seg) * TT * TT);

    float v[8], s[8], cn[8];
    float base;

    // ---------------- prologue: rows 0 and 1 ----------------
    // Row 0 DP result is exactly the (segment-wide) inclusive prefix sum.
    {
        float4 r0a = cb[2 * sl],      r0b = cb[2 * sl + 1];
        float4 r1a = cb[32 + 2 * sl], r1b = cb[32 + 2 * sl + 1];

        float a[8] = {r0a.x, r0a.y, r0a.z, r0a.w, r0b.x, r0b.y, r0b.z, r0b.w};
        float b[8] = {r1a.x, r1a.y, r1a.z, r1a.w, r1b.x, r1b.y, r1b.z, r1b.w};
        #pragma unroll
        for (int q = 1; q < 8; q++) { a[q] += a[q - 1]; b[q] += b[q - 1]; }

        float sum0 = a[7], sum1 = b[7];
        #pragma unroll
        for (int off = 1; off < 16; off <<= 1) {
            float t0 = __shfl_up_sync(FULL, sum0, off);
            float t1 = __shfl_up_sync(FULL, sum1, off);
            if (sl >= off) { sum0 += t0; sum1 += t1; }
        }
        float b0 = sum0 - a[7];   // exclusive segment prefix, row 0
        float b1 = sum1 - b[7];   // exclusive segment prefix, row 1
        #pragma unroll
        for (int q = 0; q < 8; q++) {
            v[q] = a[q] + b0;     // row-0 DP values
            s[q] = b[q] + b1;     // row-1 global prefix sums
        }
        base = b1;

        float4 c2a = cb[64 + 2 * sl], c2b = cb[64 + 2 * sl + 1];
        cn[0] = c2a.x; cn[1] = c2a.y; cn[2] = c2a.z; cn[3] = c2a.w;
        cn[4] = c2b.x; cn[5] = c2b.y; cn[6] = c2b.z; cn[7] = c2b.w;
    }

    // ---------------- main loop: rows 1..127 ----------------
    // Invariant at top: v = row (i-1) DP, s/base = row i prefix sums,
    //                   cn = row (i+1) costs.
    #pragma unroll 1
    for (int i = 1; i < TT; i++) {
        int nl = (i + 2 < TT) ? (i + 2) : (TT - 1);
        float4 fa = cb[nl * 32 + 2 * sl];
        float4 fb = cb[nl * 32 + 2 * sl + 1];

        // next-row local sums (independent of the v chain)
        float ns[8];
        ns[0] = cn[0];
        #pragma unroll
        for (int q = 1; q < 8; q++) ns[q] = ns[q - 1] + cn[q];

        // current-row min-chain setup
        float up = __shfl_up_sync(FULL, v[7], 1);
        float sh = (sl == 0) ? INFF : up;

        float m[8];
        m[0] = fminf(v[0], sh);
        #pragma unroll
        for (int q = 1; q < 8; q++) m[q] = fminf(v[q], v[q - 1]);

        float pm[8];
        pm[0] = m[0] - base;
        #pragma unroll
        for (int q = 1; q < 8; q++) pm[q] = fminf(pm[q - 1], m[q] - s[q - 1]);

        // interleaved segmented scans: +scan(next sums) and min-scan(current)
        float nsum = ns[7], mn = pm[7];
        #pragma unroll
        for (int off = 1; off < 16; off <<= 1) {
            float ta = __shfl_up_sync(FULL, nsum, off);
            float tb = __shfl_up_sync(FULL, mn, off);
            if (sl >= off) { nsum += ta; mn = fminf(mn, tb); }
        }

        float ex = __shfl_up_sync(FULL, mn, 1);   // exclusive min of preceding lanes
        if (sl == 0) ex = INFF;

        float nb = nsum - ns[7];                   // exclusive +prefix for next row

        #pragma unroll
        for (int q = 0; q < 8; q++) v[q] = s[q] + fminf(pm[q], ex);

        base = nb;
        #pragma unroll
        for (int q = 0; q < 8; q++) s[q] = ns[q] + nb;

        cn[0] = fa.x; cn[1] = fa.y; cn[2] = fa.z; cn[3] = fa.w;
        cn[4] = fb.x; cn[5] = fb.y; cn[6] = fb.z; cn[7] = fb.w;
    }

    if (sl == 15) g_dists[2 * warpId + seg] = v[7];   // D[T][T]
}

// =====================================================================
// Kernel B: exact top-K selection via rank counting (permutation ranks).
// rank(p) = #{ j : d_j < d_p or (d_j == d_p and j < p) } -> slot rank.
// Reproduces top_k's sorted-ascending, tie-by-index order.
// =====================================================================
__global__ void __launch_bounds__(256) rank_kernel() {
    __shared__ float sd[PN];
    for (int i = threadIdx.x; i < PN; i += blockDim.x) sd[i] = g_dists[i];
    __syncthreads();

    int warp = threadIdx.x >> 5;
    int lane = threadIdx.x & 31;

    #pragma unroll
    for (int e = 0; e < 4; e++) {
        int p = blockIdx.x * 32 + warp * 4 + e;
        float d = sd[p];
        int cnt = 0;
        #pragma unroll 4
        for (int j = lane; j < PN; j += 32) {
            float dj = sd[j];
            cnt += (dj < d) || (dj == d && j < p);
        }
        #pragma unroll
        for (int off = 16; off; off >>= 1)
            cnt += __shfl_down_sync(0xffffffffu, cnt, off);
        if (lane == 0 && cnt < KEL) {
            g_eidx[cnt]  = p;
            g_edist[cnt] = d;
        }
    }
}

// =====================================================================
// Kernel C: softmax-style elite scores + zero-fill the padding slots.
// =====================================================================
__global__ void __launch_bounds__(512) score_kernel() {
    __shared__ float sred[512];
    int tid = threadIdx.x;

    float d = (tid < KEL) ? g_edist[tid] : INFF;

    sred[tid] = d; __syncthreads();
    #pragma unroll
    for (int s = 256; s; s >>= 1) {
        if (tid < s) sred[tid] = fminf(sred[tid], sred[tid + s]);
        __syncthreads();
    }
    float mind = sred[0]; __syncthreads();

    float e = (tid < KEL) ? expf(0.5f * (mind - d)) : 0.0f;

    sred[tid] = e; __syncthreads();
    #pragma unroll
    for (int s = 256; s; s >>= 1) {
        if (tid < s) sred[tid] += sred[tid + s];
        __syncthreads();
    }
    float E = sred[0]; __syncthreads();

    float wk = e / E;
    if (tid < KEL) g_w[tid] = wk;
    if (tid >= KEL && tid < KPAD) { g_w[tid] = 0.0f; g_eidx[tid] = 0; }  // pad

    sred[tid] = (tid < KEL) ? wk : 0.0f; __syncthreads();
    #pragma unroll
    for (int s = 256; s; s >>= 1) {
        if (tid < s) sred[tid] += sred[tid + s];
        __syncthreads();
    }
    if (tid == 0) {
        float ssum = sred[0];
        g_scalars[0] = ssum;
        g_scalars[1] = 1.0f / (ssum + 1e-9f);
    }
}

// =====================================================================
// Kernel D: elite-gathered weighted mean/std per (t, a). One block per t,
// 1024 threads. K padded to 416 = 32*13 so each warp runs exactly 13
// fully-unrolled, INDEPENDENT smem-idx -> gather chains (max MLP).
// =====================================================================
__global__ void __launch_bounds__(1024) stats_kernel(
    const float* __restrict__ noise,   // [T, P, A]
    const float* __restrict__ means,   // [T, 1, A]
    const float* __restrict__ stds,    // [T, 1, A]
    float* __restrict__ out)           // [2, T, 1, A]
{
    int t    = blockIdx.x;
    int lane = threadIdx.x & 31;       // a index
    int warp = threadIdx.x >> 5;       // 0..31

    __shared__ float sw[KPAD];
    __shared__ int   si[KPAD];
    __shared__ float red1[32][33];     // padded: conflict-free column reads
    __shared__ float red2[32][33];

    if (threadIdx.x < KPAD) {
        sw[threadIdx.x] = g_w[threadIdx.x];
        si[threadIdx.x] = g_eidx[threadIdx.x];
    }
    __syncthreads();

    float mean_ta = means[t * AA + lane];
    float std_ta  = stds [t * AA + lane];
    const float* nbase = noise + (size_t)t * PN * AA;

    float S1 = 0.0f, S2 = 0.0f;
    #pragma unroll
    for (int it = 0; it < 13; it++) {
        int k = warp + (it << 5);      // < KPAD, exact
        float wk = sw[k];
        int   p  = si[k];
        float x  = fmaf(std_ta, __ldg(nbase + p * AA + lane), mean_ta);
        x = fminf(fmaxf(x, -1.0f), 1.0f);
        S1 += wk * x;
        S2 += wk * x * x;
    }
    red1[warp][lane] = S1;
    red2[warp][lane] = S2;
    __syncthreads();

    if (warp == 0) {
        float s1 = 0.0f, s2 = 0.0f;
        #pragma unroll
        for (int i = 0; i < 32; i++) { s1 += red1[i][lane]; s2 += red2[i][lane]; }

        float W     = g_scalars[0];
        float recip = g_scalars[1];
        float mu  = s1 * recip;
        float var = fmaxf((s2 - 2.0f * mu * s1 + mu * mu * W) * recip, 0.0f);
        float sd  = fminf(fmaxf(sqrtf(var), 0.05f), 1.0f);

        out[t * AA + lane]           = 0.1f * mean_ta + 0.9f * mu;  // means_new
        out[TT * AA + t * AA + lane] = sd;                          // _std
    }
}

// =====================================================================
extern "C" void kernel_launch(void* const* d_in, const int* in_sizes, int n_in,
                              void* d_out, int out_size) {
    const float* obs   = (const float*)d_in[0];  // [P, T, T]
    const float* means = (const float*)d_in[1];  // [T, 1, A]
    const float* stds  = (const float*)d_in[2];  // [T, 1, A]
    const float* noise = (const float*)d_in[3];  // [T, P, A]
    float* out = (float*)d_out;                  // [2, T, 1, A]

    dtw_kernel  <<<PN / 16, 256>>>(obs);   // 2048 warps, 2 problems/warp (segments)
    rank_kernel <<<PN / 32, 256>>>();
    score_kernel<<<1, 512>>>();
    stats_kernel<<<TT, 1024>>>(noise, means, stds, out);
}

// round 11
// speedup vs baseline: 1.2634x; 1.2634x over previous
#include <cuda_runtime.h>
#include <math.h>

// Problem constants
#define PN   4096
#define TT   128
#define AA   32
#define KEL  409          // int(4096 * 0.1)
#define KPAD 416          // 32 * 13, zero-weight padded
#define INFF 1e30f

// ---------------- scratch (no allocations allowed) ----------------
__device__ float g_dists[PN];
__device__ int   g_eidx[KPAD];
__device__ float g_edist[KEL];
__device__ float g_w[KPAD];
__device__ float g_scalars[2];   // [0] = ssum, [1] = 1/(ssum+1e-9)

// =====================================================================
// Kernel A: DTW min-plus DP, ONE problem per warp (R8 structure — the
// proven-fastest config: 4096 warps for latency hiding).
// Row recurrence new[j] = min(min(prev[j+1],prev[j]), new[j-1]) + c[j]
// solved per row as: s = prefix_sum(c); new[j] = s[j] + prefmin(m-s_ex).
// Lane owns 4 consecutive columns. Row i+1's +scan is computed during
// row i's min-scan with the two SHFL chains interleaved.
// NEW: register prefetch DISTANCE 4 (rows i+1..i+4 resident) so each
// warp keeps ~4 independent LDG.128 in flight -> covers ~1000cy DRAM
// latency under load instead of ~500cy.
// =====================================================================
__global__ void __launch_bounds__(256) dtw_kernel(const float* __restrict__ obs) {
    const unsigned FULL = 0xffffffffu;
    int warpId = (blockIdx.x * blockDim.x + threadIdx.x) >> 5;
    int lane   = threadIdx.x & 31;
    if (warpId >= PN) return;

    const float4* cbase = (const float4*)(obs + (size_t)warpId * TT * TT);

    // prevnew[j] = D_prev_row[j+1]
    float v0, v1, v2, v3;
    float s0, s1, s2, s3, base;

    // ---- prologue: row0 result (= prefix sum), row1 sums, prefetch 2..4 ----
    {
        float4 c0 = cbase[lane];
        float4 c1 = cbase[32 + lane];

        float a0 = c0.x, a1 = a0 + c0.y, a2 = a1 + c0.z, a3 = a2 + c0.w;
        float b0 = c1.x, b1 = b0 + c1.y, b2 = b1 + c1.z, b3 = b2 + c1.w;

        float sumA = a3, sumB = b3;
        #pragma unroll
        for (int off = 1; off < 32; off <<= 1) {
            float t0 = __shfl_up_sync(FULL, sumA, off);
            float t1 = __shfl_up_sync(FULL, sumB, off);
            if (lane >= off) { sumA += t0; sumB += t1; }
        }
        float bs0 = sumA - a3;     // exclusive base, row 0
        float bs1 = sumB - b3;     // exclusive base, row 1

        // Row-0 DP values: D[1][j+1] = prefix_sum(row0)[j]
        v0 = a0 + bs0; v1 = a1 + bs0; v2 = a2 + bs0; v3 = a3 + bs0;
        // Row-1 global prefix sums
        s0 = b0 + bs1; s1 = b1 + bs1; s2 = b2 + bs1; s3 = b3 + bs1;
        base = bs1;
    }

    // prefetch buffers: c1n = costs row i+1, c2n = i+2, c3n = i+3
    float4 c1n = cbase[2 * 32 + lane];   // row 2
    float4 c2n = cbase[3 * 32 + lane];   // row 3
    float4 c3n = cbase[4 * 32 + lane];   // row 4

    // ---- main loop: rows 1..127 ----
    // Invariant: v = row(i-1) DP, s/base = row i sums,
    //            c1n/c2n/c3n = costs rows i+1 / i+2 / i+3.
    #pragma unroll 2
    for (int i = 1; i < TT; i++) {
        int nl = (i + 4 < TT) ? (i + 4) : (TT - 1);
        float4 cf = cbase[nl * 32 + lane];          // row i+4 (clamped)

        // next-row local sums (independent of the v chain)
        float ns0 = c1n.x;
        float ns1 = ns0 + c1n.y;
        float ns2 = ns1 + c1n.z;
        float ns3 = ns2 + c1n.w;

        // current-row min-chain setup
        float up  = __shfl_up_sync(FULL, v3, 1);
        float sh0 = (lane == 0) ? INFF : up;

        float m0 = fminf(v0, sh0);
        float m1 = fminf(v1, v0);
        float m2 = fminf(v2, v1);
        float m3 = fminf(v3, v2);

        float t0 = m0 - base;
        float t1 = m1 - s0;
        float t2 = m2 - s1;
        float t3 = m3 - s2;

        float p0 = t0;
        float p1 = fminf(p0, t1);
        float p2 = fminf(p1, t2);
        float p3 = fminf(p2, t3);

        // interleaved warp scans: +scan (next sums) and min-scan (current).
        // min-scan unpredicated: OOB shfl returns own value; fmin(x,x)=x.
        float nsum = ns3;
        float mn   = p3;
        #pragma unroll
        for (int off = 1; off < 32; off <<= 1) {
            float ta = __shfl_up_sync(FULL, nsum, off);
            float tb = __shfl_up_sync(FULL, mn, off);
            if (lane >= off) nsum += ta;
            mn = fminf(mn, tb);
        }

        float ex = __shfl_up_sync(FULL, mn, 1);     // exclusive min of prior lanes
        if (lane == 0) ex = INFF;

        float nbase = nsum - ns3;                    // exclusive +prefix, next row

        v0 = s0 + fminf(p0, ex);
        v1 = s1 + fminf(p1, ex);
        v2 = s2 + fminf(p2, ex);
        v3 = s3 + fminf(p3, ex);

        base = nbase;
        s0 = ns0 + nbase;
        s1 = ns1 + nbase;
        s2 = ns2 + nbase;
        s3 = ns3 + nbase;

        // rotate prefetch pipeline
        c1n = c2n;
        c2n = c3n;
        c3n = cf;
    }

    if (lane == 31) g_dists[warpId] = v3;   // D[T][T]
}

// =====================================================================
// Kernel B: exact top-K selection via rank counting (permutation ranks).
// rank(p) = #{ j : d_j < d_p or (d_j == d_p and j < p) } -> slot rank.
// Reproduces top_k's sorted-ascending, tie-by-index order.
// =====================================================================
__global__ void __launch_bounds__(256) rank_kernel() {
    __shared__ float sd[PN];
    for (int i = threadIdx.x; i < PN; i += blockDim.x) sd[i] = g_dists[i];
    __syncthreads();

    int warp = threadIdx.x >> 5;
    int lane = threadIdx.x & 31;

    #pragma unroll
    for (int e = 0; e < 4; e++) {
        int p = blockIdx.x * 32 + warp * 4 + e;
        float d = sd[p];
        int cnt = 0;
        #pragma unroll 4
        for (int j = lane; j < PN; j += 32) {
            float dj = sd[j];
            cnt += (dj < d) || (dj == d && j < p);
        }
        #pragma unroll
        for (int off = 16; off; off >>= 1)
            cnt += __shfl_down_sync(0xffffffffu, cnt, off);
        if (lane == 0 && cnt < KEL) {
            g_eidx[cnt]  = p;
            g_edist[cnt] = d;
        }
    }
}

// =====================================================================
// Kernel C: softmax-style elite scores + zero-fill padding slots.
// =====================================================================
__global__ void __launch_bounds__(512) score_kernel() {
    __shared__ float sred[512];
    int tid = threadIdx.x;

    float d = (tid < KEL) ? g_edist[tid] : INFF;

    sred[tid] = d; __syncthreads();
    #pragma unroll
    for (int s = 256; s; s >>= 1) {
        if (tid < s) sred[tid] = fminf(sred[tid], sred[tid + s]);
        __syncthreads();
    }
    float mind = sred[0]; __syncthreads();

    float e = (tid < KEL) ? expf(0.5f * (mind - d)) : 0.0f;

    sred[tid] = e; __syncthreads();
    #pragma unroll
    for (int s = 256; s; s >>= 1) {
        if (tid < s) sred[tid] += sred[tid + s];
        __syncthreads();
    }
    float E = sred[0]; __syncthreads();

    float wk = e / E;
    if (tid < KEL) g_w[tid] = wk;
    if (tid >= KEL && tid < KPAD) { g_w[tid] = 0.0f; g_eidx[tid] = 0; }  // pad

    sred[tid] = (tid < KEL) ? wk : 0.0f; __syncthreads();
    #pragma unroll
    for (int s = 256; s; s >>= 1) {
        if (tid < s) sred[tid] += sred[tid + s];
        __syncthreads();
    }
    if (tid == 0) {
        float ssum = sred[0];
        g_scalars[0] = ssum;
        g_scalars[1] = 1.0f / (ssum + 1e-9f);
    }
}

// =====================================================================
// Kernel D: elite-gathered weighted mean/std per (t, a). One block per t,
// 1024 threads. K padded to 416 = 32*13 so each warp runs exactly 13
// fully-unrolled, INDEPENDENT smem-idx -> gather chains (max MLP).
// =====================================================================
__global__ void __launch_bounds__(1024) stats_kernel(
    const float* __restrict__ noise,   // [T, P, A]
    const float* __restrict__ means,   // [T, 1, A]
    const float* __restrict__ stds,    // [T, 1, A]
    float* __restrict__ out)           // [2, T, 1, A]
{
    int t    = blockIdx.x;
    int lane = threadIdx.x & 31;       // a index
    int warp = threadIdx.x >> 5;       // 0..31

    __shared__ float sw[KPAD];
    __shared__ int   si[KPAD];
    __shared__ float red1[32][33];     // padded: conflict-free column reads
    __shared__ float red2[32][33];

    if (threadIdx.x < KPAD) {
        sw[threadIdx.x] = g_w[threadIdx.x];
        si[threadIdx.x] = g_eidx[threadIdx.x];
    }
    __syncthreads();

    float mean_ta = means[t * AA + lane];
    float std_ta  = stds [t * AA + lane];
    const float* nbase = noise + (size_t)t * PN * AA;

    float S1 = 0.0f, S2 = 0.0f;
    #pragma unroll
    for (int it = 0; it < 13; it++) {
        int k = warp + (it << 5);      // < KPAD, exact
        float wk = sw[k];
        int   p  = si[k];
        float x  = fmaf(std_ta, __ldg(nbase + p * AA + lane), mean_ta);
        x = fminf(fmaxf(x, -1.0f), 1.0f);
        S1 += wk * x;
        S2 += wk * x * x;
    }
    red1[warp][lane] = S1;
    red2[warp][lane] = S2;
    __syncthreads();

    if (warp == 0) {
        float s1 = 0.0f, s2 = 0.0f;
        #pragma unroll
        for (int i = 0; i < 32; i++) { s1 += red1[i][lane]; s2 += red2[i][lane]; }

        float W     = g_scalars[0];
        float recip = g_scalars[1];
        float mu  = s1 * recip;
        float var = fmaxf((s2 - 2.0f * mu * s1 + mu * mu * W) * recip, 0.0f);
        float sd  = fminf(fmaxf(sqrtf(var), 0.05f), 1.0f);

        out[t * AA + lane]           = 0.1f * mean_ta + 0.9f * mu;  // means_new
        out[TT * AA + t * AA + lane] = sd;                          // _std
    }
}

// =====================================================================
extern "C" void kernel_launch(void* const* d_in, const int* in_sizes, int n_in,
                              void* d_out, int out_size) {
    const float* obs   = (const float*)d_in[0];  // [P, T, T]
    const float* means = (const float*)d_in[1];  // [T, 1, A]
    const float* stds  = (const float*)d_in[2];  // [T, 1, A]
    const float* noise = (const float*)d_in[3];  // [T, P, A]
    float* out = (float*)d_out;                  // [2, T, 1, A]

    dtw_kernel  <<<PN / 8, 256>>>(obs);    // 4096 warps, 1 problem/warp
    rank_kernel <<<PN / 32, 256>>>();
    score_kernel<<<1, 512>>>();
    stats_kernel<<<TT, 1024>>>(noise, means, stds, out);
}

// round 12
// speedup vs baseline: 1.4620x; 1.1571x over previous
#include <cuda_runtime.h>
#include <math.h>

// Problem constants
#define PN   4096
#define TT   128
#define AA   32
#define KEL  409          // int(4096 * 0.1)
#define KPAD 416          // 32 * 13, zero-weight padded
#define INFF 1e30f

// ---------------- scratch (no allocations allowed) ----------------
__device__ float g_dists[PN];
__device__ int   g_eidx[KPAD];
__device__ float g_edist[KEL];
__device__ float g_w[KPAD];
__device__ float g_scalars[2];   // [0] = ssum, [1] = 1/(ssum+1e-9)

// =====================================================================
// Kernel A: DTW min-plus DP, one warp per problem (EXACT R8 structure —
// the empirically fastest config; R9/R10/R11 variants all regressed).
// Row recurrence new[j] = min(min(prev[j+1],prev[j]), new[j-1]) + c[j]
// solved per row as: s = prefix_sum(c); new[j] = s[j] + prefmin(m-s_ex).
// Lane owns 4 consecutive columns. Row i+1's +scan is computed during
// row i's min-scan with the two 5-step SHFL chains interleaved.
// Single delta vs R8: obs loads use __ldcs (streaming, evict-first) —
// the 256MB input has zero reuse.
// =====================================================================
__global__ void __launch_bounds__(256) dtw_kernel(const float* __restrict__ obs) {
    const unsigned FULL = 0xffffffffu;
    int warpId = (blockIdx.x * blockDim.x + threadIdx.x) >> 5;
    int lane   = threadIdx.x & 31;
    if (warpId >= PN) return;

    const float4* cbase = (const float4*)(obs + (size_t)warpId * TT * TT);

    // prevnew[j] = D_prev_row[j+1]; init row0: D[0][1..128] = INF
    float v0 = INFF, v1 = INFF, v2 = INFF, v3 = INFF;
    float carry = 0.0f;      // D_prev_row[0]: 0 for first row, INF after

    // ---- prologue: sums for row 0 ----
    float4 c0 = __ldcs(cbase + lane);
    float s0 = c0.x;
    float s1 = s0 + c0.y;
    float s2 = s1 + c0.z;
    float s3 = s2 + c0.w;
    {
        float sum = s3;
        #pragma unroll
        for (int off = 1; off < 32; off <<= 1) {
            float t = __shfl_up_sync(FULL, sum, off);
            if (lane >= off) sum += t;
        }
        float base0 = sum - s3;
        s0 += base0; s1 += base0; s2 += base0; s3 += base0;
        c0.x = base0;            // stash exclusive base
    }
    float base = c0.x;

    float4 cn = __ldcs(cbase + 32 + lane);   // row 1 costs

    #pragma unroll 2
    for (int i = 0; i < TT; i++) {
        // prefetch row i+2 (clamped, unconditional -> keeps MLP up)
        int nl = (i + 2 < TT) ? (i + 2) : (TT - 1);
        float4 cf = __ldcs(cbase + nl * 32 + lane);

        // --- next-row local sums (independent of v chain) ---
        float ns0 = cn.x;
        float ns1 = ns0 + cn.y;
        float ns2 = ns1 + cn.z;
        float ns3 = ns2 + cn.w;

        // --- current-row min chain setup (depends on previous row's v) ---
        float up  = __shfl_up_sync(FULL, v3, 1);
        float sh0 = (lane == 0) ? carry : up;

        float m0 = fminf(v0, sh0);
        float m1 = fminf(v1, v0);
        float m2 = fminf(v2, v1);
        float m3 = fminf(v3, v2);

        float t0 = m0 - base;
        float t1 = m1 - s0;
        float t2 = m2 - s1;
        float t3 = m3 - s2;

        float p0 = t0;
        float p1 = fminf(p0, t1);
        float p2 = fminf(p1, t2);
        float p3 = fminf(p2, t3);

        // --- interleaved warp scans: +scan(next sums) and min-scan(current) ---
        float nsum = ns3;
        float mn   = p3;
        #pragma unroll
        for (int off = 1; off < 32; off <<= 1) {
            float ta = __shfl_up_sync(FULL, nsum, off);
            float tb = __shfl_up_sync(FULL, mn, off);
            if (lane >= off) {
                nsum += ta;
                mn    = fminf(mn, tb);
            }
        }

        float ex = __shfl_up_sync(FULL, mn, 1);   // exclusive (preceding lanes)
        if (lane == 0) ex = INFF;

        float nbase = nsum - ns3;                  // exclusive +prefix for next row

        v0 = s0 + fminf(p0, ex);
        v1 = s1 + fminf(p1, ex);
        v2 = s2 + fminf(p2, ex);
        v3 = s3 + fminf(p3, ex);

        // rotate pipeline state
        base = nbase;
        s0 = ns0 + nbase;
        s1 = ns1 + nbase;
        s2 = ns2 + nbase;
        s3 = ns3 + nbase;
        carry = INFF;
        cn = cf;
    }

    if (lane == 31) g_dists[warpId] = v3;   // D[T][T]
}

// =====================================================================
// Kernel B: exact top-K selection via rank counting (permutation ranks).
// rank(p) = #{ j : d_j < d_p or (d_j == d_p and j < p) } -> slot rank.
// Reproduces top_k's sorted-ascending, tie-by-index order.
// =====================================================================
__global__ void __launch_bounds__(256) rank_kernel() {
    __shared__ float sd[PN];
    for (int i = threadIdx.x; i < PN; i += blockDim.x) sd[i] = g_dists[i];
    __syncthreads();

    int warp = threadIdx.x >> 5;
    int lane = threadIdx.x & 31;

    #pragma unroll
    for (int e = 0; e < 4; e++) {
        int p = blockIdx.x * 32 + warp * 4 + e;
        float d = sd[p];
        int cnt = 0;
        #pragma unroll 4
        for (int j = lane; j < PN; j += 32) {
            float dj = sd[j];
            cnt += (dj < d) || (dj == d && j < p);
        }
        #pragma unroll
        for (int off = 16; off; off >>= 1)
            cnt += __shfl_down_sync(0xffffffffu, cnt, off);
        if (lane == 0 && cnt < KEL) {
            g_eidx[cnt]  = p;
            g_edist[cnt] = d;
        }
    }
}

// =====================================================================
// Kernel C: softmax-style elite scores + zero-fill padding slots.
// =====================================================================
__global__ void __launch_bounds__(512) score_kernel() {
    __shared__ float sred[512];
    int tid = threadIdx.x;

    float d = (tid < KEL) ? g_edist[tid] : INFF;

    sred[tid] = d; __syncthreads();
    #pragma unroll
    for (int s = 256; s; s >>= 1) {
        if (tid < s) sred[tid] = fminf(sred[tid], sred[tid + s]);
        __syncthreads();
    }
    float mind = sred[0]; __syncthreads();

    float e = (tid < KEL) ? expf(0.5f * (mind - d)) : 0.0f;

    sred[tid] = e; __syncthreads();
    #pragma unroll
    for (int s = 256; s; s >>= 1) {
        if (tid < s) sred[tid] += sred[tid + s];
        __syncthreads();
    }
    float E = sred[0]; __syncthreads();

    float wk = e / E;
    if (tid < KEL) g_w[tid] = wk;
    if (tid >= KEL && tid < KPAD) { g_w[tid] = 0.0f; g_eidx[tid] = 0; }  // pad

    sred[tid] = (tid < KEL) ? wk : 0.0f; __syncthreads();
    #pragma unroll
    for (int s = 256; s; s >>= 1) {
        if (tid < s) sred[tid] += sred[tid + s];
        __syncthreads();
    }
    if (tid == 0) {
        float ssum = sred[0];
        g_scalars[0] = ssum;
        g_scalars[1] = 1.0f / (ssum + 1e-9f);
    }
}

// =====================================================================
// Kernel D: elite-gathered weighted mean/std per (t, a). One block per t,
// 1024 threads. K padded to 416 = 32*13 so each warp runs exactly 13
// fully-unrolled, INDEPENDENT smem-idx -> gather chains (max MLP).
// =====================================================================
__global__ void __launch_bounds__(1024) stats_kernel(
    const float* __restrict__ noise,   // [T, P, A]
    const float* __restrict__ means,   // [T, 1, A]
    const float* __restrict__ stds,    // [T, 1, A]
    float* __restrict__ out)           // [2, T, 1, A]
{
    int t    = blockIdx.x;
    int lane = threadIdx.x & 31;       // a index
    int warp = threadIdx.x >> 5;       // 0..31

    __shared__ float sw[KPAD];
    __shared__ int   si[KPAD];
    __shared__ float red1[32][33];     // padded: conflict-free column reads
    __shared__ float red2[32][33];

    if (threadIdx.x < KPAD) {
        sw[threadIdx.x] = g_w[threadIdx.x];
        si[threadIdx.x] = g_eidx[threadIdx.x];
    }
    __syncthreads();

    float mean_ta = means[t * AA + lane];
    float std_ta  = stds [t * AA + lane];
    const float* nbase = noise + (size_t)t * PN * AA;

    float S1 = 0.0f, S2 = 0.0f;
    #pragma unroll
    for (int it = 0; it < 13; it++) {
        int k = warp + (it << 5);      // < KPAD, exact
        float wk = sw[k];
        int   p  = si[k];
        float x  = fmaf(std_ta, __ldg(nbase + p * AA + lane), mean_ta);
        x = fminf(fmaxf(x, -1.0f), 1.0f);
        S1 += wk * x;
        S2 += wk * x * x;
    }
    red1[warp][lane] = S1;
    red2[warp][lane] = S2;
    __syncthreads();

    if (warp == 0) {
        float s1 = 0.0f, s2 = 0.0f;
        #pragma unroll
        for (int i = 0; i < 32; i++) { s1 += red1[i][lane]; s2 += red2[i][lane]; }

        float W     = g_scalars[0];
        float recip = g_scalars[1];
        float mu  = s1 * recip;
        float var = fmaxf((s2 - 2.0f * mu * s1 + mu * mu * W) * recip, 0.0f);
        float sd  = fminf(fmaxf(sqrtf(var), 0.05f), 1.0f);

        out[t * AA + lane]           = 0.1f * mean_ta + 0.9f * mu;  // means_new
        out[TT * AA + t * AA + lane] = sd;                          // _std
    }
}

// =====================================================================
extern "C" void kernel_launch(void* const* d_in, const int* in_sizes, int n_in,
                              void* d_out, int out_size) {
    const float* obs   = (const float*)d_in[0];  // [P, T, T]
    const float* means = (const float*)d_in[1];  // [T, 1, A]
    const float* stds  = (const float*)d_in[2];  // [T, 1, A]
    const float* noise = (const float*)d_in[3];  // [T, P, A]
    float* out = (float*)d_out;                  // [2, T, 1, A]

    dtw_kernel  <<<PN / 8, 256>>>(obs);    // 4096 warps, 1 problem/warp
    rank_kernel <<<PN / 32, 256>>>();
    score_kernel<<<1, 512>>>();
    stats_kernel<<<TT, 1024>>>(noise, means, stds, out);
}

// round 13
// speedup vs baseline: 1.4852x; 1.0159x over previous
#include <cuda_runtime.h>
#include <math.h>

// Problem constants
#define PN   4096
#define TT   128
#define AA   32
#define KEL  409          // int(4096 * 0.1)
#define KPAD 416          // 32 * 13, zero-weight padded
#define INFF 1e30f

// ---------------- scratch (no allocations allowed) ----------------
__device__ float g_dists[PN];
__device__ int   g_eidx[KPAD];
__device__ float g_edist[KEL];
__device__ float g_w[KPAD];
__device__ float g_scalars[2];   // [0] = ssum, [1] = 1/(ssum+1e-9)

// =====================================================================
// Kernel A: DTW min-plus DP, one warp per problem (EXACT R8 structure —
// the empirically fastest config; R9/R10/R11 variants all regressed).
// Row recurrence new[j] = min(min(prev[j+1],prev[j]), new[j-1]) + c[j]
// solved per row as: s = prefix_sum(c); new[j] = s[j] + prefmin(m-s_ex).
// Lane owns 4 consecutive columns. Row i+1's +scan is computed during
// row i's min-scan with the two 5-step SHFL chains interleaved.
// Single delta vs R8: obs loads use __ldcs (streaming, evict-first) —
// the 256MB input has zero reuse.
// =====================================================================
__global__ void __launch_bounds__(256) dtw_kernel(const float* __restrict__ obs) {
    const unsigned FULL = 0xffffffffu;
    int warpId = (blockIdx.x * blockDim.x + threadIdx.x) >> 5;
    int lane   = threadIdx.x & 31;
    if (warpId >= PN) return;

    const float4* cbase = (const float4*)(obs + (size_t)warpId * TT * TT);

    // prevnew[j] = D_prev_row[j+1]; init row0: D[0][1..128] = INF
    float v0 = INFF, v1 = INFF, v2 = INFF, v3 = INFF;
    float carry = 0.0f;      // D_prev_row[0]: 0 for first row, INF after

    // ---- prologue: sums for row 0 ----
    float4 c0 = __ldcs(cbase + lane);
    float s0 = c0.x;
    float s1 = s0 + c0.y;
    float s2 = s1 + c0.z;
    float s3 = s2 + c0.w;
    {
        float sum = s3;
        #pragma unroll
        for (int off = 1; off < 32; off <<= 1) {
            float t = __shfl_up_sync(FULL, sum, off);
            if (lane >= off) sum += t;
        }
        float base0 = sum - s3;
        s0 += base0; s1 += base0; s2 += base0; s3 += base0;
        c0.x = base0;            // stash exclusive base
    }
    float base = c0.x;

    float4 cn = __ldcs(cbase + 32 + lane);   // row 1 costs

    #pragma unroll 2
    for (int i = 0; i < TT; i++) {
        // prefetch row i+2 (clamped, unconditional -> keeps MLP up)
        int nl = (i + 2 < TT) ? (i + 2) : (TT - 1);
        float4 cf = __ldcs(cbase + nl * 32 + lane);

        // --- next-row local sums (independent of v chain) ---
        float ns0 = cn.x;
        float ns1 = ns0 + cn.y;
        float ns2 = ns1 + cn.z;
        float ns3 = ns2 + cn.w;

        // --- current-row min chain setup (depends on previous row's v) ---
        float up  = __shfl_up_sync(FULL, v3, 1);
        float sh0 = (lane == 0) ? carry : up;

        float m0 = fminf(v0, sh0);
        float m1 = fminf(v1, v0);
        float m2 = fminf(v2, v1);
        float m3 = fminf(v3, v2);

        float t0 = m0 - base;
        float t1 = m1 - s0;
        float t2 = m2 - s1;
        float t3 = m3 - s2;

        float p0 = t0;
        float p1 = fminf(p0, t1);
        float p2 = fminf(p1, t2);
        float p3 = fminf(p2, t3);

        // --- interleaved warp scans: +scan(next sums) and min-scan(current) ---
        float nsum = ns3;
        float mn   = p3;
        #pragma unroll
        for (int off = 1; off < 32; off <<= 1) {
            float ta = __shfl_up_sync(FULL, nsum, off);
            float tb = __shfl_up_sync(FULL, mn, off);
            if (lane >= off) {
                nsum += ta;
                mn    = fminf(mn, tb);
            }
        }

        float ex = __shfl_up_sync(FULL, mn, 1);   // exclusive (preceding lanes)
        if (lane == 0) ex = INFF;

        float nbase = nsum - ns3;                  // exclusive +prefix for next row

        v0 = s0 + fminf(p0, ex);
        v1 = s1 + fminf(p1, ex);
        v2 = s2 + fminf(p2, ex);
        v3 = s3 + fminf(p3, ex);

        // rotate pipeline state
        base = nbase;
        s0 = ns0 + nbase;
        s1 = ns1 + nbase;
        s2 = ns2 + nbase;
        s3 = ns3 + nbase;
        carry = INFF;
        cn = cf;
    }

    if (lane == 31) g_dists[warpId] = v3;   // D[T][T]
}

// =====================================================================
// Kernel B: exact top-K selection via rank counting (permutation ranks).
// rank(p) = #{ j : d_j < d_p or (d_j == d_p and j < p) } -> slot rank.
// Reproduces top_k's sorted-ascending, tie-by-index order.
// =====================================================================
__global__ void __launch_bounds__(256) rank_kernel() {
    __shared__ float sd[PN];
    for (int i = threadIdx.x; i < PN; i += blockDim.x) sd[i] = g_dists[i];
    __syncthreads();

    int warp = threadIdx.x >> 5;
    int lane = threadIdx.x & 31;

    #pragma unroll
    for (int e = 0; e < 4; e++) {
        int p = blockIdx.x * 32 + warp * 4 + e;
        float d = sd[p];
        int cnt = 0;
        #pragma unroll 4
        for (int j = lane; j < PN; j += 32) {
            float dj = sd[j];
            cnt += (dj < d) || (dj == d && j < p);
        }
        #pragma unroll
        for (int off = 16; off; off >>= 1)
            cnt += __shfl_down_sync(0xffffffffu, cnt, off);
        if (lane == 0 && cnt < KEL) {
            g_eidx[cnt]  = p;
            g_edist[cnt] = d;
        }
    }
}

// =====================================================================
// Kernel C: softmax-style elite scores + zero-fill padding slots.
// =====================================================================
__global__ void __launch_bounds__(512) score_kernel() {
    __shared__ float sred[512];
    int tid = threadIdx.x;

    float d = (tid < KEL) ? g_edist[tid] : INFF;

    sred[tid] = d; __syncthreads();
    #pragma unroll
    for (int s = 256; s; s >>= 1) {
        if (tid < s) sred[tid] = fminf(sred[tid], sred[tid + s]);
        __syncthreads();
    }
    float mind = sred[0]; __syncthreads();

    float e = (tid < KEL) ? expf(0.5f * (mind - d)) : 0.0f;

    sred[tid] = e; __syncthreads();
    #pragma unroll
    for (int s = 256; s; s >>= 1) {
        if (tid < s) sred[tid] += sred[tid + s];
        __syncthreads();
    }
    float E = sred[0]; __syncthreads();

    float wk = e / E;
    if (tid < KEL) g_w[tid] = wk;
    if (tid >= KEL && tid < KPAD) { g_w[tid] = 0.0f; g_eidx[tid] = 0; }  // pad

    sred[tid] = (tid < KEL) ? wk : 0.0f; __syncthreads();
    #pragma unroll
    for (int s = 256; s; s >>= 1) {
        if (tid < s) sred[tid] += sred[tid + s];
        __syncthreads();
    }
    if (tid == 0) {
        float ssum = sred[0];
        g_scalars[0] = ssum;
        g_scalars[1] = 1.0f / (ssum + 1e-9f);
    }
}

// =====================================================================
// Kernel D: elite-gathered weighted mean/std per (t, a). One block per t,
// 1024 threads. K padded to 416 = 32*13 so each warp runs exactly 13
// fully-unrolled, INDEPENDENT smem-idx -> gather chains (max MLP).
// =====================================================================
__global__ void __launch_bounds__(1024) stats_kernel(
    const float* __restrict__ noise,   // [T, P, A]
    const float* __restrict__ means,   // [T, 1, A]
    const float* __restrict__ stds,    // [T, 1, A]
    float* __restrict__ out)           // [2, T, 1, A]
{
    int t    = blockIdx.x;
    int lane = threadIdx.x & 31;       // a index
    int warp = threadIdx.x >> 5;       // 0..31

    __shared__ float sw[KPAD];
    __shared__ int   si[KPAD];
    __shared__ float red1[32][33];     // padded: conflict-free column reads
    __shared__ float red2[32][33];

    if (threadIdx.x < KPAD) {
        sw[threadIdx.x] = g_w[threadIdx.x];
        si[threadIdx.x] = g_eidx[threadIdx.x];
    }
    __syncthreads();

    float mean_ta = means[t * AA + lane];
    float std_ta  = stds [t * AA + lane];
    const float* nbase = noise + (size_t)t * PN * AA;

    float S1 = 0.0f, S2 = 0.0f;
    #pragma unroll
    for (int it = 0; it < 13; it++) {
        int k = warp + (it << 5);      // < KPAD, exact
        float wk = sw[k];
        int   p  = si[k];
        float x  = fmaf(std_ta, __ldg(nbase + p * AA + lane), mean_ta);
        x = fminf(fmaxf(x, -1.0f), 1.0f);
        S1 += wk * x;
        S2 += wk * x * x;
    }
    red1[warp][lane] = S1;
    red2[warp][lane] = S2;
    __syncthreads();

    if (warp == 0) {
        float s1 = 0.0f, s2 = 0.0f;
        #pragma unroll
        for (int i = 0; i < 32; i++) { s1 += red1[i][lane]; s2 += red2[i][lane]; }

        float W     = g_scalars[0];
        float recip = g_scalars[1];
        float mu  = s1 * recip;
        float var = fmaxf((s2 - 2.0f * mu * s1 + mu * mu * W) * recip, 0.0f);
        float sd  = fminf(fmaxf(sqrtf(var), 0.05f), 1.0f);

        out[t * AA + lane]           = 0.1f * mean_ta + 0.9f * mu;  // means_new
        out[TT * AA + t * AA + lane] = sd;                          // _std
    }
}

// =====================================================================
extern "C" void kernel_launch(void* const* d_in, const int* in_sizes, int n_in,
                              void* d_out, int out_size) {
    const float* obs   = (const float*)d_in[0];  // [P, T, T]
    const float* means = (const float*)d_in[1];  // [T, 1, A]
    const float* stds  = (const float*)d_in[2];  // [T, 1, A]
    const float* noise = (const float*)d_in[3];  // [T, P, A]
    float* out = (float*)d_out;                  // [2, T, 1, A]

    dtw_kernel  <<<PN / 8, 256>>>(obs);    // 4096 warps, 1 problem/warp
    rank_kernel <<<PN / 32, 256>>>();
    score_kernel<<<1, 512>>>();
    stats_kernel<<<TT, 1024>>>(noise, means, stds, out);
}

// round 14
// speedup vs baseline: 1.4906x; 1.0037x over previous
#include <cuda_runtime.h>
#include <math.h>

// Problem constants
#define PN   4096
#define TT   128
#define AA   32
#define KEL  409          // int(4096 * 0.1)
#define KPAD 416          // 32 * 13, zero-weight padded
#define INFF 1e30f

// ---------------- scratch (no allocations allowed) ----------------
__device__ float g_dists[PN];
__device__ int   g_eidx[KEL];      // elite indices, rank order (top_k order)
__device__ float g_edist[KEL];     // elite dists, rank order
__device__ int   g_sidx[KPAD];     // elite indices sorted ASCENDING BY INDEX
__device__ float g_sw[KPAD];       // weights permuted to match g_sidx
__device__ float g_scalars[2];     // [0] = ssum, [1] = 1/(ssum+1e-9)

// =====================================================================
// Kernel A: DTW min-plus DP, one warp per problem (EXACT R13 version —
// the empirically fastest config; frozen).
// =====================================================================
__global__ void __launch_bounds__(256) dtw_kernel(const float* __restrict__ obs) {
    const unsigned FULL = 0xffffffffu;
    int warpId = (blockIdx.x * blockDim.x + threadIdx.x) >> 5;
    int lane   = threadIdx.x & 31;
    if (warpId >= PN) return;

    const float4* cbase = (const float4*)(obs + (size_t)warpId * TT * TT);

    float v0 = INFF, v1 = INFF, v2 = INFF, v3 = INFF;
    float carry = 0.0f;

    float4 c0 = __ldcs(cbase + lane);
    float s0 = c0.x;
    float s1 = s0 + c0.y;
    float s2 = s1 + c0.z;
    float s3 = s2 + c0.w;
    {
        float sum = s3;
        #pragma unroll
        for (int off = 1; off < 32; off <<= 1) {
            float t = __shfl_up_sync(FULL, sum, off);
            if (lane >= off) sum += t;
        }
        float base0 = sum - s3;
        s0 += base0; s1 += base0; s2 += base0; s3 += base0;
        c0.x = base0;
    }
    float base = c0.x;

    float4 cn = __ldcs(cbase + 32 + lane);

    #pragma unroll 2
    for (int i = 0; i < TT; i++) {
        int nl = (i + 2 < TT) ? (i + 2) : (TT - 1);
        float4 cf = __ldcs(cbase + nl * 32 + lane);

        float ns0 = cn.x;
        float ns1 = ns0 + cn.y;
        float ns2 = ns1 + cn.z;
        float ns3 = ns2 + cn.w;

        float up  = __shfl_up_sync(FULL, v3, 1);
        float sh0 = (lane == 0) ? carry : up;

        float m0 = fminf(v0, sh0);
        float m1 = fminf(v1, v0);
        float m2 = fminf(v2, v1);
        float m3 = fminf(v3, v2);

        float t0 = m0 - base;
        float t1 = m1 - s0;
        float t2 = m2 - s1;
        float t3 = m3 - s2;

        float p0 = t0;
        float p1 = fminf(p0, t1);
        float p2 = fminf(p1, t2);
        float p3 = fminf(p2, t3);

        float nsum = ns3;
        float mn   = p3;
        #pragma unroll
        for (int off = 1; off < 32; off <<= 1) {
            float ta = __shfl_up_sync(FULL, nsum, off);
            float tb = __shfl_up_sync(FULL, mn, off);
            if (lane >= off) {
                nsum += ta;
                mn    = fminf(mn, tb);
            }
        }

        float ex = __shfl_up_sync(FULL, mn, 1);
        if (lane == 0) ex = INFF;

        float nbase = nsum - ns3;

        v0 = s0 + fminf(p0, ex);
        v1 = s1 + fminf(p1, ex);
        v2 = s2 + fminf(p2, ex);
        v3 = s3 + fminf(p3, ex);

        base = nbase;
        s0 = ns0 + nbase;
        s1 = ns1 + nbase;
        s2 = ns2 + nbase;
        s3 = ns3 + nbase;
        carry = INFF;
        cn = cf;
    }

    if (lane == 31) g_dists[warpId] = v3;
}

// =====================================================================
// Kernel B: exact top-K selection via rank counting (unchanged).
// =====================================================================
__global__ void __launch_bounds__(256) rank_kernel() {
    __shared__ float sd[PN];
    for (int i = threadIdx.x; i < PN; i += blockDim.x) sd[i] = g_dists[i];
    __syncthreads();

    int warp = threadIdx.x >> 5;
    int lane = threadIdx.x & 31;

    #pragma unroll
    for (int e = 0; e < 4; e++) {
        int p = blockIdx.x * 32 + warp * 4 + e;
        float d = sd[p];
        int cnt = 0;
        #pragma unroll 4
        for (int j = lane; j < PN; j += 32) {
            float dj = sd[j];
            cnt += (dj < d) || (dj == d && j < p);
        }
        #pragma unroll
        for (int off = 16; off; off >>= 1)
            cnt += __shfl_down_sync(0xffffffffu, cnt, off);
        if (lane == 0 && cnt < KEL) {
            g_eidx[cnt]  = p;
            g_edist[cnt] = d;
        }
    }
}

// =====================================================================
// Kernel C: softmax elite scores + INDEX-SORTED re-emission.
// The weighted sums downstream are permutation-invariant, so we emit
// (idx, w) sorted ascending by idx via a 4096-bit mask + popcount
// prefix — O(1) work per elite. This makes the stats gather stream
// memory in ascending order (DRAM row locality).
// =====================================================================
__global__ void __launch_bounds__(512) score_kernel() {
    __shared__ float sred[512];
    __shared__ unsigned mask[PN / 32];   // 128 words
    __shared__ int wordpfx[PN / 32];     // exclusive popcount prefix
    int tid = threadIdx.x;

    float d = (tid < KEL) ? g_edist[tid] : INFF;
    int   idx = (tid < KEL) ? g_eidx[tid] : 0;

    if (tid < PN / 32) mask[tid] = 0u;

    // min reduce
    sred[tid] = d; __syncthreads();
    #pragma unroll
    for (int s = 256; s; s >>= 1) {
        if (tid < s) sred[tid] = fminf(sred[tid], sred[tid + s]);
        __syncthreads();
    }
    float mind = sred[0]; __syncthreads();

    float e = (tid < KEL) ? expf(0.5f * (mind - d)) : 0.0f;

    // sum reduce of e; also build the elite index bitmask
    sred[tid] = e;
    if (tid < KEL) atomicOr(&mask[idx >> 5], 1u << (idx & 31));
    __syncthreads();
    #pragma unroll
    for (int s = 256; s; s >>= 1) {
        if (tid < s) sred[tid] += sred[tid + s];
        __syncthreads();
    }
    float E = sred[0]; __syncthreads();

    float wk = e / E;

    // exclusive popcount prefix over the 128 mask words (warp 0)
    if (tid < 32) {
        const unsigned FULL = 0xffffffffu;
        int b = tid * 4;
        int c0 = __popc(mask[b]);
        int c1 = __popc(mask[b + 1]);
        int c2 = __popc(mask[b + 2]);
        int c3 = __popc(mask[b + 3]);
        int tot = c0 + c1 + c2 + c3;
        int run = tot;
        #pragma unroll
        for (int off = 1; off < 32; off <<= 1) {
            int t = __shfl_up_sync(FULL, run, off);
            if (tid >= off) run += t;
        }
        int excl = run - tot;
        wordpfx[b]     = excl;
        wordpfx[b + 1] = excl + c0;
        wordpfx[b + 2] = excl + c0 + c1;
        wordpfx[b + 3] = excl + c0 + c1 + c2;
    }

    // ssum = sum of normalized scores (matches reference recompute)
    sred[tid] = (tid < KEL) ? wk : 0.0f; __syncthreads();
    #pragma unroll
    for (int s = 256; s; s >>= 1) {
        if (tid < s) sred[tid] += sred[tid + s];
        __syncthreads();
    }
    if (tid == 0) {
        float ssum = sred[0];
        g_scalars[0] = ssum;
        g_scalars[1] = 1.0f / (ssum + 1e-9f);
    }

    // scatter (idx, w) to its index-sorted position
    if (tid < KEL) {
        int word = idx >> 5, bit = idx & 31;
        int pos = wordpfx[word] + __popc(mask[word] & ((1u << bit) - 1u));
        g_sidx[pos] = idx;
        g_sw[pos]   = wk;
    }
    if (tid >= KEL && tid < KPAD) { g_sw[tid] = 0.0f; g_sidx[tid] = 0; }  // pad
}

// =====================================================================
// Kernel D: elite-gathered weighted mean/std per (t, a). One block per t,
// 1024 threads. Each warp takes a CONTIGUOUS chunk of 13 index-sorted
// elites -> its 13 independent 128B gathers walk an ascending ~16KB
// window (DRAM row locality) instead of random 40KB strides.
// =====================================================================
__global__ void __launch_bounds__(1024) stats_kernel(
    const float* __restrict__ noise,   // [T, P, A]
    const float* __restrict__ means,   // [T, 1, A]
    const float* __restrict__ stds,    // [T, 1, A]
    float* __restrict__ out)           // [2, T, 1, A]
{
    int t    = blockIdx.x;
    int lane = threadIdx.x & 31;       // a index
    int warp = threadIdx.x >> 5;       // 0..31

    __shared__ float sw[KPAD];
    __shared__ int   si[KPAD];
    __shared__ float red1[32][33];
    __shared__ float red2[32][33];

    if (threadIdx.x < KPAD) {
        sw[threadIdx.x] = g_sw[threadIdx.x];
        si[threadIdx.x] = g_sidx[threadIdx.x];
    }
    __syncthreads();

    float mean_ta = means[t * AA + lane];
    float std_ta  = stds [t * AA + lane];
    const float* nbase = noise + (size_t)t * PN * AA;

    float S1 = 0.0f, S2 = 0.0f;
    int k0 = warp * 13;                // contiguous ascending chunk
    #pragma unroll
    for (int it = 0; it < 13; it++) {
        int k = k0 + it;               // < KPAD, exact
        float wk = sw[k];
        int   p  = si[k];
        float x  = fmaf(std_ta, __ldg(nbase + p * AA + lane), mean_ta);
        x = fminf(fmaxf(x, -1.0f), 1.0f);
        S1 += wk * x;
        S2 += wk * x * x;
    }
    red1[warp][lane] = S1;
    red2[warp][lane] = S2;
    __syncthreads();

    if (warp == 0) {
        float s1 = 0.0f, s2 = 0.0f;
        #pragma unroll
        for (int i = 0; i < 32; i++) { s1 += red1[i][lane]; s2 += red2[i][lane]; }

        float W     = g_scalars[0];
        float recip = g_scalars[1];
        float mu  = s1 * recip;
        float var = fmaxf((s2 - 2.0f * mu * s1 + mu * mu * W) * recip, 0.0f);
        float sd  = fminf(fmaxf(sqrtf(var), 0.05f), 1.0f);

        out[t * AA + lane]           = 0.1f * mean_ta + 0.9f * mu;  // means_new
        out[TT * AA + t * AA + lane] = sd;                          // _std
    }
}

// =====================================================================
extern "C" void kernel_launch(void* const* d_in, const int* in_sizes, int n_in,
                              void* d_out, int out_size) {
    const float* obs   = (const float*)d_in[0];  // [P, T, T]
    const float* means = (const float*)d_in[1];  // [T, 1, A]
    const float* stds  = (const float*)d_in[2];  // [T, 1, A]
    const float* noise = (const float*)d_in[3];  // [T, P, A]
    float* out = (float*)d_out;                  // [2, T, 1, A]

    dtw_kernel  <<<PN / 8, 256>>>(obs);    // 4096 warps, 1 problem/warp
    rank_kernel <<<PN / 32, 256>>>();
    score_kernel<<<1, 512>>>();
    stats_kernel<<<TT, 1024>>>(noise, means, stds, out);
}